// round 12
// baseline (speedup 1.0000x reference)
#include <cuda_runtime.h>

// Problem constants (fixed by this dataset instance)
#define ITERS 5
#define NV 68      // base VNs
#define MC 46      // base CNs
#define ZL 384     // lifting size
#define NE 368     // edges (= MC*8, regular degree-8 checks by construction)
#define BB 64      // batch
#define ZW (ZL/4)  // 96 words per (logical) edge row
#define ZL2 (2*ZL) // doubled edge-row length (wrap-free reads)
#define ZW2 (2*ZW)

// Persistent scratch (no allocations allowed)
__device__ __align__(16) signed char g_extq[BB * NE * ZL2];   // C2V, 2*q in [-15,15], DOUBLED rows
__device__ __align__(16) float       g_tot [BB * NV * ZL2];   // beliefs, DOUBLED rows [b][n][2*ZL]
// CN-ordered per-edge metadata (uniform per CN-block in k_cn)
__device__ int g_czo[NE];   // vn*2*ZL + (ZL - shift)  -> wrap-free gather base
__device__ int g_ceo[NE];   // e * 2*ZL
// VN CSR for k_vn
__device__ int g_vnptr[NV + 1];
__device__ int g_vpack[NE]; // VN-order: (e*2*ZL) | shift<<20  (wrap-free)

// ---------------------------------------------------------------------------
// Setup: build CN-ordered metadata arrays and VN-CSR (deterministic).
// ---------------------------------------------------------------------------
__global__ void k_setup(const int* __restrict__ evn, const int* __restrict__ ecn,
                        const int* __restrict__ esh) {
    __shared__ int s_vn[NE], s_cn[NE], s_sh[NE];
    __shared__ int ccnt[MC], vcnt[NV];
    __shared__ int cbase[MC], vbase[NV];
    int t = threadIdx.x;
    if (t < NE) { s_vn[t] = evn[t]; s_cn[t] = ecn[t]; s_sh[t] = esh[t]; }
    if (t < MC) ccnt[t] = 0;
    if (t < NV) vcnt[t] = 0;
    __syncthreads();
    if (t < NE) { atomicAdd(&ccnt[s_cn[t]], 1); atomicAdd(&vcnt[s_vn[t]], 1); }
    __syncthreads();
    if (t == 0) {
        int run = 0;
        for (int c = 0; c < MC; ++c) { cbase[c] = run; run += ccnt[c]; }
        run = 0;
        for (int n = 0; n < NV; ++n) { vbase[n] = run; g_vnptr[n] = run; run += vcnt[n]; }
        g_vnptr[NV] = run;
    }
    __syncthreads();
    if (t < NE) {
        int c = s_cn[t], v = s_vn[t];
        int pc = 0, pv = 0;
        for (int e2 = 0; e2 < t; ++e2) {     // stable (e-ascending) position
            pc += (s_cn[e2] == c);
            pv += (s_vn[e2] == v);
        }
        const int pos = cbase[c] + pc;
        g_czo[pos] = v * ZL2 + (ZL - s_sh[t]);
        g_ceo[pos] = t * ZL2;
        g_vpack[vbase[v] + pv] = (t * ZL2) | (s_sh[t] << 20);
    }
}

// ---------------------------------------------------------------------------
// Prime: tot = xa, written doubled (both row halves). One-shot before iter 0.
// ---------------------------------------------------------------------------
__global__ __launch_bounds__(512) void k_prime(const float* __restrict__ xa) {
    const int idx = blockIdx.x * 512 + threadIdx.x;   // over BB*NV*ZW quads
    if (idx >= BB * NV * ZW) return;
    const int row = idx / ZW;       // b*NV + n
    const int q = idx - row * ZW;
    const float4 v = ((const float4*)xa)[idx];
    float4* __restrict__ d = (float4*)g_tot + (size_t)row * ZW2;
    d[q] = v;
    d[q + ZW] = v;
}

// ---------------------------------------------------------------------------
// VN update, z-quad per thread. Wrap-free gather (doubled extq rows); edge
// loop in chunks of 4 with split issue/consume passes (8 loads in flight).
// Integer accumulation is exact. 256-thread blocks (8 quads x 32 n-groups),
// grid (12, BB) for high occupancy. Writes tot DOUBLED and optionally
// out[it-1][b][z][n] via shared transpose.
// ---------------------------------------------------------------------------
__global__ __launch_bounds__(256, 6) void k_vn(const float* __restrict__ xa,
                                               float* __restrict__ out_prev,
                                               int write_out, int write_tot) {
    __shared__ __align__(16) float s[NV][36];    // 8 quads * 4 z + pad
    __shared__ int svptr[NV + 1];
    __shared__ int svpack[NE];
    const int tx = threadIdx.x;           // quad within tile (8)
    const int ty = threadIdx.y;           // n-group (32)
    const int tid = ty * 8 + tx;
    const int b = blockIdx.y;
    const int q0 = blockIdx.x * 8;        // quad tile base
    const int q = q0 + tx;
    const int z4 = q * 4;

    for (int i = tid; i <= NV; i += 256) svptr[i] = g_vnptr[i];
    for (int i = tid; i < NE; i += 256) svpack[i] = g_vpack[i];
    __syncthreads();

    const signed char* __restrict__ eq = g_extq + (size_t)b * (NE * ZL2);
    float* __restrict__ tb = g_tot + (size_t)b * (NV * ZL2);

    for (int n = ty; n < NV; n += 32) {
        float4 ch = ((const float4*)xa)[((size_t)b * NV + n) * ZW + q];
        int a0 = 0, a1 = 0, a2 = 0, a3 = 0;   // exact integer sums
        int j = svptr[n];
        const int j1 = svptr[n + 1];
        while (j < j1) {
            const int cnt = j1 - j;            // >=1
            unsigned ua[4], ub[4];
            int sh[4];
#pragma unroll
            for (int k = 0; k < 4; ++k) {
                if (k < cnt) {
                    const int pk = svpack[j + k];
                    const int zc = z4 + (pk >> 20);          // <= 763 < 768, no wrap
                    const unsigned* __restrict__ row =
                        (const unsigned*)(eq + (pk & 0xFFFFF));
                    const int w0 = zc >> 2;                  // w0+1 <= 191, no wrap
                    ua[k] = row[w0];
                    ub[k] = row[w0 + 1];
                    sh[k] = (zc & 3) * 8;
                }
            }
#pragma unroll
            for (int k = 0; k < 4; ++k) {
                if (k < cnt) {
                    const unsigned u = __funnelshift_r(ua[k], ub[k], sh[k]);
                    a0 += (int)(signed char)(u);
                    a1 += (int)(signed char)(u >> 8);
                    a2 += (int)(signed char)(u >> 16);
                    a3 += (int)(signed char)(u >> 24);
                }
            }
            j += 4;
        }
        ch.x += 0.5f * (float)a0;
        ch.y += 0.5f * (float)a1;
        ch.z += 0.5f * (float)a2;
        ch.w += 0.5f * (float)a3;
        if (write_tot) {
            float4* __restrict__ tr = (float4*)tb + n * ZW2;
            tr[q] = ch;
            tr[q + ZW] = ch;
        }
        *(float4*)&s[n][tx * 4] = ch;
    }
    if (write_out) {
        __syncthreads();
        float4* __restrict__ dst = (float4*)(out_prev + ((size_t)b * ZL + q0 * 4) * NV);
        // 32 z-rows x 17 float4 per row (NV=68)
        for (int f = tid; f < 32 * 17; f += 256) {
            const int zl = f / 17;
            const int n0 = (f - zl * 17) * 4;
            float4 o;
            o.x = s[n0 + 0][zl]; o.y = s[n0 + 1][zl];
            o.z = s[n0 + 2][zl]; o.w = s[n0 + 3][zl];
            dst[f] = o;
        }
    }
}

// ---------------------------------------------------------------------------
// CN update (min-sum, reference-exact tie semantics) + LUT quantizer.
// One block per (CN, batch): 192 threads = 192 z-pairs. Doubled tot rows ->
// wrap-free gather; writes state DUPLICATED (z2 and z2+ZL) so k_vn's gather
// is wrap-free too. Output pair = one byte_perm over {+m1,-m1,+m2,-m2} LUTs.
// ---------------------------------------------------------------------------
__global__ __launch_bounds__(192, 6) void k_cn(const float* __restrict__ cnw,
                                               int it, int first) {
    __shared__ int szo[8], seo[8];
    const int tid = threadIdx.x;
    const int c = blockIdx.x;
    const int b = blockIdx.y;
    if (tid < 8) {
        szo[tid] = g_czo[c * 8 + tid];
        seo[tid] = g_ceo[c * 8 + tid];
    }
    __syncthreads();

    const int z2 = tid * 2;
    const float w = __ldg(&cnw[it]);
    const float w2m = fabsf(w + w);
    const unsigned wsb = __float_as_uint(w) & 0x80000000u;
    const float* __restrict__ tbr = g_tot + (size_t)b * (NV * ZL2);
    signed char* __restrict__ eqz = g_extq + (size_t)b * (NE * ZL2) + z2;

    // Pass A: batch all loads (16 tot floats + 8 state shorts in flight)
    float t0[8], t1[8];
    int es[8];
#pragma unroll
    for (int j = 0; j < 8; ++j) {
        const int za = szo[j] + z2;        // wrap-free (doubled rows)
        t0[j] = tbr[za];
        t1[j] = tbr[za + 1];
        es[j] = first ? 0 : (int)*(const short*)(eqz + seo[j]);
    }
    // Pass B: extrinsic beliefs, sign XOR, min1
    float v0[8], v1[8];
    unsigned s0 = wsb, s1 = wsb;          // running sign XOR (w sign folded)
    float m10 = 1e30f, m11 = 1e30f;
#pragma unroll
    for (int j = 0; j < 8; ++j) {
        const float c0 = 0.5f * (float)((signed char)(es[j]));
        const float c1 = 0.5f * (float)((signed char)(es[j] >> 8));
        const float a0 = fminf(fmaxf(t0[j] - c0, -20.f), 20.f);
        const float a1 = fminf(fmaxf(t1[j] - c1, -20.f), 20.f);
        v0[j] = a0; v1[j] = a1;
        s0 ^= __float_as_uint(a0);
        s1 ^= __float_as_uint(a1);
        m10 = fminf(m10, fabsf(a0));
        m11 = fminf(m11, fabsf(a1));
    }
    float m20 = 1e9f, m21 = 1e9f;         // BIG, matches reference when all tie
#pragma unroll
    for (int j = 0; j < 8; ++j) {
        float a;
        a = fabsf(v0[j]); if (a != m10) m20 = fminf(m20, a);
        a = fabsf(v1[j]); if (a != m11) m21 = fminf(m21, a);
    }
    // Quantized magnitudes (stored value = 2*q in [-15,15]):
    // __float2int_rn = round-half-even; clip-then-round == round-then-clip @15.
    const int i10 = __float2int_rn(fminf(w2m * m10, 15.f));
    const int i20 = __float2int_rn(fminf(w2m * m20, 15.f));
    const int i11 = __float2int_rn(fminf(w2m * m11, 15.f));
    const int i21 = __float2int_rn(fminf(w2m * m21, 15.f));
    // Per-lane byte LUT: [ +m1, -m1, +m2, -m2 ]
    const unsigned lut0 = (unsigned)i10 | (((unsigned)(-i10) & 0xff) << 8)
                        | ((unsigned)i20 << 16) | (((unsigned)(-i20) & 0xff) << 24);
    const unsigned lut1 = (unsigned)i11 | (((unsigned)(-i11) & 0xff) << 8)
                        | ((unsigned)i21 << 16) | (((unsigned)(-i21) & 0xff) << 24);
#pragma unroll
    for (int j = 0; j < 8; ++j) {
        const unsigned u0 = s0 ^ __float_as_uint(v0[j]);
        const unsigned u1 = s1 ^ __float_as_uint(v1[j]);
        int idx0 = (int)(u0 >> 31);       // sign bit
        if (fabsf(v0[j]) == m10) idx0 |= 2;   // is-min -> use m2
        int idx1 = (int)(u1 >> 31) | 4;   // select from lut1
        if (fabsf(v1[j]) == m11) idx1 |= 2;
        const unsigned r = __byte_perm(lut0, lut1, (unsigned)(idx0 | (idx1 << 4)));
        *(short*)(eqz + seo[j]) = (short)r;          // copy 1
        *(short*)(eqz + seo[j] + ZL) = (short)r;     // copy 2 (wrap-free reads)
    }
}

// ---------------------------------------------------------------------------
extern "C" void kernel_launch(void* const* d_in, const int* in_sizes, int n_in,
                              void* d_out, int out_size) {
    const float* xa  = (const float*)d_in[0];   // [B, N, Z] f32
    const float* cnw = (const float*)d_in[1];   // [ITERS] f32
    const int* evn   = (const int*)d_in[2];     // [E] i32
    const int* ecn   = (const int*)d_in[3];     // [E] i32
    const int* esh   = (const int*)d_in[4];     // [E] i32
    float* out = (float*)d_out;                 // [ITERS, B, Z, N] f32

    k_setup<<<1, 384>>>(evn, ecn, esh);
    k_prime<<<(BB * NV * ZW + 511) / 512, 512>>>(xa);   // tot = xa (doubled rows)

    dim3 blkV(8, 32);
    dim3 gV(12, BB);                // 12 quad-tiles of 8 quads (32 z) x batch
    dim3 gC(MC, BB);                // one block per (CN, batch), 192 z-pairs

    for (int it = 0; it < ITERS; ++it) {
        k_cn<<<gC, 192>>>(cnw, it, it == 0);
        // VN pass of iteration it+1 writes out[it] (== marginalized output of
        // it); the last one needs no tot for a subsequent CN pass.
        k_vn<<<gV, blkV>>>(xa, out + (size_t)it * BB * ZL * NV, 1,
                           it != ITERS - 1);
    }
}

// round 13
// speedup vs baseline: 1.0442x; 1.0442x over previous
#include <cuda_runtime.h>

// Problem constants (fixed by this dataset instance)
#define ITERS 5
#define NV 68      // base VNs
#define MC 46      // base CNs
#define ZL 384     // lifting size
#define NE 368     // edges (= MC*8, regular degree-8 checks by construction)
#define BB 64      // batch
#define ZW (ZL/4)  // 96 words per (logical) edge row
#define ZL2 (2*ZL) // doubled edge-row length (wrap-free reads)
#define ZW2 (2*ZW)

// Persistent scratch (no allocations allowed)
__device__ __align__(16) signed char g_extq[BB * NE * ZL2];   // C2V, 2*q in [-15,15], DOUBLED rows
__device__ __align__(16) float       g_tot [BB * NV * ZL2];   // beliefs, DOUBLED rows [b][n][2*ZL]
// CN-ordered per-edge metadata (uniform per CN-block in k_cn)
__device__ int g_czo[NE];   // vn*2*ZL + (ZL - shift)  -> wrap-free gather base
__device__ int g_ceo[NE];   // e * 2*ZL
// VN CSR for k_vn
__device__ int g_vnptr[NV + 1];
__device__ int g_vpack[NE]; // VN-order: (e*2*ZL) | shift<<20  (wrap-free)

// ---------------------------------------------------------------------------
// Setup: build CN-ordered metadata arrays and VN-CSR (deterministic).
// ---------------------------------------------------------------------------
__global__ void k_setup(const int* __restrict__ evn, const int* __restrict__ ecn,
                        const int* __restrict__ esh) {
    __shared__ int s_vn[NE], s_cn[NE], s_sh[NE];
    __shared__ int ccnt[MC], vcnt[NV];
    __shared__ int cbase[MC], vbase[NV];
    int t = threadIdx.x;
    if (t < NE) { s_vn[t] = evn[t]; s_cn[t] = ecn[t]; s_sh[t] = esh[t]; }
    if (t < MC) ccnt[t] = 0;
    if (t < NV) vcnt[t] = 0;
    __syncthreads();
    if (t < NE) { atomicAdd(&ccnt[s_cn[t]], 1); atomicAdd(&vcnt[s_vn[t]], 1); }
    __syncthreads();
    if (t == 0) {
        int run = 0;
        for (int c = 0; c < MC; ++c) { cbase[c] = run; run += ccnt[c]; }
        run = 0;
        for (int n = 0; n < NV; ++n) { vbase[n] = run; g_vnptr[n] = run; run += vcnt[n]; }
        g_vnptr[NV] = run;
    }
    __syncthreads();
    if (t < NE) {
        int c = s_cn[t], v = s_vn[t];
        int pc = 0, pv = 0;
        for (int e2 = 0; e2 < t; ++e2) {     // stable (e-ascending) position
            pc += (s_cn[e2] == c);
            pv += (s_vn[e2] == v);
        }
        const int pos = cbase[c] + pc;
        g_czo[pos] = v * ZL2 + (ZL - s_sh[t]);
        g_ceo[pos] = t * ZL2;
        g_vpack[vbase[v] + pv] = (t * ZL2) | (s_sh[t] << 20);
    }
}

// ---------------------------------------------------------------------------
// Prime: tot = xa, written doubled (both row halves). One-shot before iter 0.
// ---------------------------------------------------------------------------
__global__ __launch_bounds__(512) void k_prime(const float* __restrict__ xa) {
    const int idx = blockIdx.x * 512 + threadIdx.x;   // over BB*NV*ZW quads
    if (idx >= BB * NV * ZW) return;
    const int row = idx / ZW;       // b*NV + n
    const int q = idx - row * ZW;
    const float4 v = ((const float4*)xa)[idx];
    float4* __restrict__ d = (float4*)g_tot + (size_t)row * ZW2;
    d[q] = v;
    d[q + ZW] = v;
}

// ---------------------------------------------------------------------------
// VN update, z-quad per thread. Wrap-free gather (doubled extq rows); edge
// loop in chunks of 4 with split issue/consume passes (8 loads in flight).
// Integer accumulation is exact. 512-thread blocks (16 quads x 32 n-groups),
// grid (6, BB) = 384 blocks; 3 blocks/SM -> single wave on 148 SMs.
// Writes tot DOUBLED and optionally out[it-1][b][z][n] via shared transpose.
// ---------------------------------------------------------------------------
__global__ __launch_bounds__(512, 3) void k_vn(const float* __restrict__ xa,
                                               float* __restrict__ out_prev,
                                               int write_out, int write_tot) {
    __shared__ __align__(16) float s[NV][68];    // padded transpose rows
    __shared__ int svptr[NV + 1];
    __shared__ int svpack[NE];
    const int tx = threadIdx.x;           // quad within tile (16)
    const int ty = threadIdx.y;           // n-group (32)
    const int tid = ty * 16 + tx;
    const int b = blockIdx.y;
    const int q0 = blockIdx.x * 16;       // quad tile base
    const int q = q0 + tx;
    const int z4 = q * 4;

    for (int i = tid; i <= NV; i += 512) svptr[i] = g_vnptr[i];
    for (int i = tid; i < NE; i += 512) svpack[i] = g_vpack[i];
    __syncthreads();

    const signed char* __restrict__ eq = g_extq + (size_t)b * (NE * ZL2);
    float* __restrict__ tb = g_tot + (size_t)b * (NV * ZL2);

    for (int n = ty; n < NV; n += 32) {
        float4 ch = ((const float4*)xa)[((size_t)b * NV + n) * ZW + q];
        int a0 = 0, a1 = 0, a2 = 0, a3 = 0;   // exact integer sums
        int j = svptr[n];
        const int j1 = svptr[n + 1];
        while (j < j1) {
            const int cnt = j1 - j;            // >=1
            unsigned ua[4], ub[4];
            int sh[4];
#pragma unroll
            for (int k = 0; k < 4; ++k) {
                if (k < cnt) {
                    const int pk = svpack[j + k];
                    const int zc = z4 + (pk >> 20);          // <= 763 < 768, no wrap
                    const unsigned* __restrict__ row =
                        (const unsigned*)(eq + (pk & 0xFFFFF));
                    const int w0 = zc >> 2;                  // w0+1 <= 191, no wrap
                    ua[k] = row[w0];
                    ub[k] = row[w0 + 1];
                    sh[k] = (zc & 3) * 8;
                }
            }
#pragma unroll
            for (int k = 0; k < 4; ++k) {
                if (k < cnt) {
                    const unsigned u = __funnelshift_r(ua[k], ub[k], sh[k]);
                    a0 += (int)(signed char)(u);
                    a1 += (int)(signed char)(u >> 8);
                    a2 += (int)(signed char)(u >> 16);
                    a3 += (int)(signed char)(u >> 24);
                }
            }
            j += 4;
        }
        ch.x += 0.5f * (float)a0;
        ch.y += 0.5f * (float)a1;
        ch.z += 0.5f * (float)a2;
        ch.w += 0.5f * (float)a3;
        if (write_tot) {
            float4* __restrict__ tr = (float4*)tb + n * ZW2;
            tr[q] = ch;
            tr[q + ZW] = ch;
        }
        *(float4*)&s[n][tx * 4] = ch;
    }
    if (write_out) {
        __syncthreads();
        float4* __restrict__ dst = (float4*)(out_prev + ((size_t)b * ZL + q0 * 4) * NV);
        // 64 z-rows x 17 float4 per row (NV=68)
        for (int f = tid; f < 64 * 17; f += 512) {
            const int zl = f / 17;
            const int n0 = (f - zl * 17) * 4;
            float4 o;
            o.x = s[n0 + 0][zl]; o.y = s[n0 + 1][zl];
            o.z = s[n0 + 2][zl]; o.w = s[n0 + 3][zl];
            dst[f] = o;
        }
    }
}

// ---------------------------------------------------------------------------
// CN update (min-sum, reference-exact tie semantics) + LUT quantizer.
// One block per (CN, batch): 192 threads = 192 z-pairs. Doubled tot rows ->
// wrap-free gather; writes state DUPLICATED (z2 and z2+ZL) so k_vn's gather
// is wrap-free too. Output pair = one byte_perm over {+m1,-m1,+m2,-m2} LUTs.
// ---------------------------------------------------------------------------
__global__ __launch_bounds__(192, 6) void k_cn(const float* __restrict__ cnw,
                                               int it, int first) {
    __shared__ int szo[8], seo[8];
    const int tid = threadIdx.x;
    const int c = blockIdx.x;
    const int b = blockIdx.y;
    if (tid < 8) {
        szo[tid] = g_czo[c * 8 + tid];
        seo[tid] = g_ceo[c * 8 + tid];
    }
    __syncthreads();

    const int z2 = tid * 2;
    const float w = __ldg(&cnw[it]);
    const float w2m = fabsf(w + w);
    const unsigned wsb = __float_as_uint(w) & 0x80000000u;
    const float* __restrict__ tbr = g_tot + (size_t)b * (NV * ZL2);
    signed char* __restrict__ eqz = g_extq + (size_t)b * (NE * ZL2) + z2;

    // Pass A: batch all loads (16 tot floats + 8 state shorts in flight)
    float t0[8], t1[8];
    int es[8];
#pragma unroll
    for (int j = 0; j < 8; ++j) {
        const int za = szo[j] + z2;        // wrap-free (doubled rows)
        t0[j] = tbr[za];
        t1[j] = tbr[za + 1];
        es[j] = first ? 0 : (int)*(const short*)(eqz + seo[j]);
    }
    // Pass B: extrinsic beliefs, sign XOR, min1
    float v0[8], v1[8];
    unsigned s0 = wsb, s1 = wsb;          // running sign XOR (w sign folded)
    float m10 = 1e30f, m11 = 1e30f;
#pragma unroll
    for (int j = 0; j < 8; ++j) {
        const float c0 = 0.5f * (float)((signed char)(es[j]));
        const float c1 = 0.5f * (float)((signed char)(es[j] >> 8));
        const float a0 = fminf(fmaxf(t0[j] - c0, -20.f), 20.f);
        const float a1 = fminf(fmaxf(t1[j] - c1, -20.f), 20.f);
        v0[j] = a0; v1[j] = a1;
        s0 ^= __float_as_uint(a0);
        s1 ^= __float_as_uint(a1);
        m10 = fminf(m10, fabsf(a0));
        m11 = fminf(m11, fabsf(a1));
    }
    float m20 = 1e9f, m21 = 1e9f;         // BIG, matches reference when all tie
#pragma unroll
    for (int j = 0; j < 8; ++j) {
        float a;
        a = fabsf(v0[j]); if (a != m10) m20 = fminf(m20, a);
        a = fabsf(v1[j]); if (a != m11) m21 = fminf(m21, a);
    }
    // Quantized magnitudes (stored value = 2*q in [-15,15]):
    // __float2int_rn = round-half-even; clip-then-round == round-then-clip @15.
    const int i10 = __float2int_rn(fminf(w2m * m10, 15.f));
    const int i20 = __float2int_rn(fminf(w2m * m20, 15.f));
    const int i11 = __float2int_rn(fminf(w2m * m11, 15.f));
    const int i21 = __float2int_rn(fminf(w2m * m21, 15.f));
    // Per-lane byte LUT: [ +m1, -m1, +m2, -m2 ]
    const unsigned lut0 = (unsigned)i10 | (((unsigned)(-i10) & 0xff) << 8)
                        | ((unsigned)i20 << 16) | (((unsigned)(-i20) & 0xff) << 24);
    const unsigned lut1 = (unsigned)i11 | (((unsigned)(-i11) & 0xff) << 8)
                        | ((unsigned)i21 << 16) | (((unsigned)(-i21) & 0xff) << 24);
#pragma unroll
    for (int j = 0; j < 8; ++j) {
        const unsigned u0 = s0 ^ __float_as_uint(v0[j]);
        const unsigned u1 = s1 ^ __float_as_uint(v1[j]);
        int idx0 = (int)(u0 >> 31);       // sign bit
        if (fabsf(v0[j]) == m10) idx0 |= 2;   // is-min -> use m2
        int idx1 = (int)(u1 >> 31) | 4;   // select from lut1
        if (fabsf(v1[j]) == m11) idx1 |= 2;
        const unsigned r = __byte_perm(lut0, lut1, (unsigned)(idx0 | (idx1 << 4)));
        *(short*)(eqz + seo[j]) = (short)r;          // copy 1
        *(short*)(eqz + seo[j] + ZL) = (short)r;     // copy 2 (wrap-free reads)
    }
}

// ---------------------------------------------------------------------------
extern "C" void kernel_launch(void* const* d_in, const int* in_sizes, int n_in,
                              void* d_out, int out_size) {
    const float* xa  = (const float*)d_in[0];   // [B, N, Z] f32
    const float* cnw = (const float*)d_in[1];   // [ITERS] f32
    const int* evn   = (const int*)d_in[2];     // [E] i32
    const int* ecn   = (const int*)d_in[3];     // [E] i32
    const int* esh   = (const int*)d_in[4];     // [E] i32
    float* out = (float*)d_out;                 // [ITERS, B, Z, N] f32

    k_setup<<<1, 384>>>(evn, ecn, esh);
    k_prime<<<(BB * NV * ZW + 511) / 512, 512>>>(xa);   // tot = xa (doubled rows)

    dim3 blkV(16, 32);
    dim3 gV(6, BB);                 // 6 quad-tiles of 16 quads (64 z) x batch
    dim3 gC(MC, BB);                // one block per (CN, batch), 192 z-pairs

    for (int it = 0; it < ITERS; ++it) {
        k_cn<<<gC, 192>>>(cnw, it, it == 0);
        // VN pass of iteration it+1 writes out[it] (== marginalized output of
        // it); the last one needs no tot for a subsequent CN pass.
        k_vn<<<gV, blkV>>>(xa, out + (size_t)it * BB * ZL * NV, 1,
                           it != ITERS - 1);
    }
}

// round 14
// speedup vs baseline: 1.0506x; 1.0061x over previous
#include <cuda_runtime.h>

// Problem constants (fixed by this dataset instance)
#define ITERS 5
#define NV 68      // base VNs
#define MC 46      // base CNs
#define ZL 384     // lifting size
#define NE 368     // edges (= MC*8, regular degree-8 checks by construction)
#define BB 64      // batch
#define ZW (ZL/4)  // 96 words per (logical) edge row
#define ZL2 (2*ZL) // doubled edge-row length (wrap-free reads)
#define ZW2 (2*ZW)
#define SEGW 17    // staged words per edge segment (64 z + shift slack)

// Persistent scratch (no allocations allowed)
__device__ __align__(16) signed char g_extq[BB * NE * ZL2];   // C2V, 2*q in [-15,15], DOUBLED rows
__device__ __align__(16) float       g_tot [BB * NV * ZL2];   // beliefs, DOUBLED rows [b][n][2*ZL]
// CN-ordered per-edge metadata (uniform per CN-block in k_cn)
__device__ int g_czo[NE];   // vn*2*ZL + (ZL - shift)  -> wrap-free gather base
__device__ int g_ceo[NE];   // e * 2*ZL
// VN CSR for k_vn
__device__ int g_vnptr[NV + 1];
__device__ int g_vpack[NE]; // VN-order: (e*2*ZL) | shift<<20  (wrap-free)

// ---------------------------------------------------------------------------
// Setup: build CN-ordered metadata arrays and VN-CSR (deterministic).
// ---------------------------------------------------------------------------
__global__ void k_setup(const int* __restrict__ evn, const int* __restrict__ ecn,
                        const int* __restrict__ esh) {
    __shared__ int s_vn[NE], s_cn[NE], s_sh[NE];
    __shared__ int ccnt[MC], vcnt[NV];
    __shared__ int cbase[MC], vbase[NV];
    int t = threadIdx.x;
    if (t < NE) { s_vn[t] = evn[t]; s_cn[t] = ecn[t]; s_sh[t] = esh[t]; }
    if (t < MC) ccnt[t] = 0;
    if (t < NV) vcnt[t] = 0;
    __syncthreads();
    if (t < NE) { atomicAdd(&ccnt[s_cn[t]], 1); atomicAdd(&vcnt[s_vn[t]], 1); }
    __syncthreads();
    if (t == 0) {
        int run = 0;
        for (int c = 0; c < MC; ++c) { cbase[c] = run; run += ccnt[c]; }
        run = 0;
        for (int n = 0; n < NV; ++n) { vbase[n] = run; g_vnptr[n] = run; run += vcnt[n]; }
        g_vnptr[NV] = run;
    }
    __syncthreads();
    if (t < NE) {
        int c = s_cn[t], v = s_vn[t];
        int pc = 0, pv = 0;
        for (int e2 = 0; e2 < t; ++e2) {     // stable (e-ascending) position
            pc += (s_cn[e2] == c);
            pv += (s_vn[e2] == v);
        }
        const int pos = cbase[c] + pc;
        g_czo[pos] = v * ZL2 + (ZL - s_sh[t]);
        g_ceo[pos] = t * ZL2;
        g_vpack[vbase[v] + pv] = (t * ZL2) | (s_sh[t] << 20);
    }
}

// ---------------------------------------------------------------------------
// Prime: tot = xa, written doubled (both row halves). One-shot before iter 0.
// ---------------------------------------------------------------------------
__global__ __launch_bounds__(512) void k_prime(const float* __restrict__ xa) {
    const int idx = blockIdx.x * 512 + threadIdx.x;   // over BB*NV*ZW quads
    if (idx >= BB * NV * ZW) return;
    const int row = idx / ZW;       // b*NV + n
    const int q = idx - row * ZW;
    const float4 v = ((const float4*)xa)[idx];
    float4* __restrict__ d = (float4*)g_tot + (size_t)row * ZW2;
    d[q] = v;
    d[q + ZW] = v;
}

// ---------------------------------------------------------------------------
// VN update with shared-memory edge staging. Each block (b, 64-z tile) first
// cooperatively stages the 17 words of every edge row it needs (one batched
// L2 round trip), then all gathers are LDS: per edge 2 LDS + funnelshift +
// 4 sign-extract adds. Integer accumulation is exact (messages = 2*q).
// Writes tot DOUBLED and out[it-1][b][z][n] via shared transpose.
// ---------------------------------------------------------------------------
__global__ __launch_bounds__(512, 3) void k_vn(const float* __restrict__ xa,
                                               float* __restrict__ out_prev,
                                               int write_out, int write_tot) {
    __shared__ __align__(16) float s[NV][68];    // padded transpose rows
    __shared__ unsigned seg[NE * SEGW];          // staged edge segments (25 KB)
    __shared__ int svptr[NV + 1];
    __shared__ int svpack[NE];
    const int tx = threadIdx.x;           // quad within tile (16)
    const int ty = threadIdx.y;           // n-group (32)
    const int tid = ty * 16 + tx;
    const int b = blockIdx.y;
    const int q0 = blockIdx.x * 16;       // quad tile base
    const int q = q0 + tx;
    const int z0 = q0 * 4;                // z tile base

    for (int i = tid; i <= NV; i += 512) svptr[i] = g_vnptr[i];
    for (int i = tid; i < NE; i += 512) svpack[i] = g_vpack[i];
    __syncthreads();

    // Stage: seg[j*17 + w] = word (z0+sh_j)/4 + w of edge j's doubled row.
    // Max word index = (z0+sh)/4 + 16 <= 191 < 192, always in-bounds.
    const unsigned* __restrict__ eqw =
        (const unsigned*)(g_extq + (size_t)b * (NE * ZL2));
#pragma unroll
    for (int p = 0; p < 13; ++p) {
        const int idx = tid + p * 512;
        if (idx < NE * SEGW) {
            const int j = idx / SEGW;
            const int w = idx - j * SEGW;
            const int pk = svpack[j];
            const int wbase = ((pk & 0xFFFFF) >> 2) + ((z0 + (pk >> 20)) >> 2);
            seg[idx] = eqw[wbase + w];
        }
    }
    __syncthreads();

    float* __restrict__ tb = g_tot + (size_t)b * (NV * ZL2);

    for (int n = ty; n < NV; n += 32) {
        float4 ch = ((const float4*)xa)[((size_t)b * NV + n) * ZW + q];
        int a0 = 0, a1 = 0, a2 = 0, a3 = 0;   // exact integer sums
        const int j1 = svptr[n + 1];
        for (int j = svptr[n]; j < j1; ++j) {
            const int sh8 = ((svpack[j] >> 20) & 3) * 8;
            const unsigned ua = seg[j * SEGW + tx];
            const unsigned ub = seg[j * SEGW + tx + 1];
            const unsigned u = __funnelshift_r(ua, ub, sh8);
            a0 += (int)(signed char)(u);
            a1 += (int)(signed char)(u >> 8);
            a2 += (int)(signed char)(u >> 16);
            a3 += (int)(signed char)(u >> 24);
        }
        ch.x += 0.5f * (float)a0;
        ch.y += 0.5f * (float)a1;
        ch.z += 0.5f * (float)a2;
        ch.w += 0.5f * (float)a3;
        if (write_tot) {
            float4* __restrict__ tr = (float4*)tb + n * ZW2;
            tr[q] = ch;
            tr[q + ZW] = ch;
        }
        *(float4*)&s[n][tx * 4] = ch;
    }
    if (write_out) {
        __syncthreads();
        float4* __restrict__ dst = (float4*)(out_prev + ((size_t)b * ZL + z0) * NV);
        // 64 z-rows x 17 float4 per row (NV=68)
        for (int f = tid; f < 64 * 17; f += 512) {
            const int zl = f / 17;
            const int n0 = (f - zl * 17) * 4;
            float4 o;
            o.x = s[n0 + 0][zl]; o.y = s[n0 + 1][zl];
            o.z = s[n0 + 2][zl]; o.w = s[n0 + 3][zl];
            dst[f] = o;
        }
    }
}

// ---------------------------------------------------------------------------
// CN update (min-sum, reference-exact tie semantics) + LUT quantizer.
// One block per (CN, batch): 192 threads = 192 z-pairs. Doubled tot rows ->
// wrap-free gather; writes state DUPLICATED (z2 and z2+ZL) so k_vn's gather
// is wrap-free too. Output pair = one byte_perm over {+m1,-m1,+m2,-m2} LUTs.
// ---------------------------------------------------------------------------
__global__ __launch_bounds__(192, 6) void k_cn(const float* __restrict__ cnw,
                                               int it, int first) {
    __shared__ int szo[8], seo[8];
    const int tid = threadIdx.x;
    const int c = blockIdx.x;
    const int b = blockIdx.y;
    if (tid < 8) {
        szo[tid] = g_czo[c * 8 + tid];
        seo[tid] = g_ceo[c * 8 + tid];
    }
    __syncthreads();

    const int z2 = tid * 2;
    const float w = __ldg(&cnw[it]);
    const float w2m = fabsf(w + w);
    const unsigned wsb = __float_as_uint(w) & 0x80000000u;
    const float* __restrict__ tbr = g_tot + (size_t)b * (NV * ZL2);
    signed char* __restrict__ eqz = g_extq + (size_t)b * (NE * ZL2) + z2;

    // Pass A: batch all loads (16 tot floats + 8 state shorts in flight)
    float t0[8], t1[8];
    int es[8];
#pragma unroll
    for (int j = 0; j < 8; ++j) {
        const int za = szo[j] + z2;        // wrap-free (doubled rows)
        t0[j] = tbr[za];
        t1[j] = tbr[za + 1];
        es[j] = first ? 0 : (int)*(const short*)(eqz + seo[j]);
    }
    // Pass B: extrinsic beliefs, sign XOR, min1
    float v0[8], v1[8];
    unsigned s0 = wsb, s1 = wsb;          // running sign XOR (w sign folded)
    float m10 = 1e30f, m11 = 1e30f;
#pragma unroll
    for (int j = 0; j < 8; ++j) {
        const float c0 = 0.5f * (float)((signed char)(es[j]));
        const float c1 = 0.5f * (float)((signed char)(es[j] >> 8));
        const float a0 = fminf(fmaxf(t0[j] - c0, -20.f), 20.f);
        const float a1 = fminf(fmaxf(t1[j] - c1, -20.f), 20.f);
        v0[j] = a0; v1[j] = a1;
        s0 ^= __float_as_uint(a0);
        s1 ^= __float_as_uint(a1);
        m10 = fminf(m10, fabsf(a0));
        m11 = fminf(m11, fabsf(a1));
    }
    float m20 = 1e9f, m21 = 1e9f;         // BIG, matches reference when all tie
#pragma unroll
    for (int j = 0; j < 8; ++j) {
        float a;
        a = fabsf(v0[j]); if (a != m10) m20 = fminf(m20, a);
        a = fabsf(v1[j]); if (a != m11) m21 = fminf(m21, a);
    }
    // Quantized magnitudes (stored value = 2*q in [-15,15]):
    // __float2int_rn = round-half-even; clip-then-round == round-then-clip @15.
    const int i10 = __float2int_rn(fminf(w2m * m10, 15.f));
    const int i20 = __float2int_rn(fminf(w2m * m20, 15.f));
    const int i11 = __float2int_rn(fminf(w2m * m11, 15.f));
    const int i21 = __float2int_rn(fminf(w2m * m21, 15.f));
    // Per-lane byte LUT: [ +m1, -m1, +m2, -m2 ]
    const unsigned lut0 = (unsigned)i10 | (((unsigned)(-i10) & 0xff) << 8)
                        | ((unsigned)i20 << 16) | (((unsigned)(-i20) & 0xff) << 24);
    const unsigned lut1 = (unsigned)i11 | (((unsigned)(-i11) & 0xff) << 8)
                        | ((unsigned)i21 << 16) | (((unsigned)(-i21) & 0xff) << 24);
#pragma unroll
    for (int j = 0; j < 8; ++j) {
        const unsigned u0 = s0 ^ __float_as_uint(v0[j]);
        const unsigned u1 = s1 ^ __float_as_uint(v1[j]);
        int idx0 = (int)(u0 >> 31);       // sign bit
        if (fabsf(v0[j]) == m10) idx0 |= 2;   // is-min -> use m2
        int idx1 = (int)(u1 >> 31) | 4;   // select from lut1
        if (fabsf(v1[j]) == m11) idx1 |= 2;
        const unsigned r = __byte_perm(lut0, lut1, (unsigned)(idx0 | (idx1 << 4)));
        *(short*)(eqz + seo[j]) = (short)r;          // copy 1
        *(short*)(eqz + seo[j] + ZL) = (short)r;     // copy 2 (wrap-free reads)
    }
}

// ---------------------------------------------------------------------------
extern "C" void kernel_launch(void* const* d_in, const int* in_sizes, int n_in,
                              void* d_out, int out_size) {
    const float* xa  = (const float*)d_in[0];   // [B, N, Z] f32
    const float* cnw = (const float*)d_in[1];   // [ITERS] f32
    const int* evn   = (const int*)d_in[2];     // [E] i32
    const int* ecn   = (const int*)d_in[3];     // [E] i32
    const int* esh   = (const int*)d_in[4];     // [E] i32
    float* out = (float*)d_out;                 // [ITERS, B, Z, N] f32

    k_setup<<<1, 384>>>(evn, ecn, esh);
    k_prime<<<(BB * NV * ZW + 511) / 512, 512>>>(xa);   // tot = xa (doubled rows)

    dim3 blkV(16, 32);
    dim3 gV(6, BB);                 // 6 quad-tiles of 16 quads (64 z) x batch
    dim3 gC(MC, BB);                // one block per (CN, batch), 192 z-pairs

    for (int it = 0; it < ITERS; ++it) {
        k_cn<<<gC, 192>>>(cnw, it, it == 0);
        // VN pass of iteration it+1 writes out[it] (== marginalized output of
        // it); the last one needs no tot for a subsequent CN pass.
        k_vn<<<gV, blkV>>>(xa, out + (size_t)it * BB * ZL * NV, 1,
                           it != ITERS - 1);
    }
}

// round 15
// speedup vs baseline: 1.1001x; 1.0471x over previous
#include <cuda_runtime.h>

// Problem constants (fixed by this dataset instance)
#define ITERS 5
#define NV 68      // base VNs
#define MC 46      // base CNs
#define ZL 384     // lifting size
#define NE 368     // edges (= MC*8, regular degree-8 checks by construction)
#define BB 64      // batch
#define ZW (ZL/4)  // 96 words per (logical) edge row
#define ZL2 (2*ZL) // doubled edge-row length (wrap-free reads)
#define ZW2 (2*ZW)
#define SEGP 17    // segment pitch in words (16 used; odd pitch = conflict-free)

// Persistent scratch (no allocations allowed)
__device__ __align__(16) signed char g_extq[BB * NE * ZL2];   // C2V, 2*q in [-15,15], DOUBLED rows
__device__ __align__(16) float       g_tot [BB * NV * ZL2];   // beliefs, DOUBLED rows [b][n][2*ZL]
// CN-ordered per-edge metadata (uniform per CN-block in k_cn)
__device__ int g_czo[NE];   // vn*2*ZL + (ZL - shift)  -> wrap-free gather base
__device__ int g_ceo[NE];   // e * 2*ZL
// VN CSR for k_vn
__device__ int g_vnptr[NV + 1];
__device__ int g_vpack[NE]; // VN-order: (e*2*ZL) | shift<<20  (wrap-free)

// ---------------------------------------------------------------------------
// Setup: build CN-ordered metadata arrays and VN-CSR (deterministic).
// ---------------------------------------------------------------------------
__global__ void k_setup(const int* __restrict__ evn, const int* __restrict__ ecn,
                        const int* __restrict__ esh) {
    __shared__ int s_vn[NE], s_cn[NE], s_sh[NE];
    __shared__ int ccnt[MC], vcnt[NV];
    __shared__ int cbase[MC], vbase[NV];
    int t = threadIdx.x;
    if (t < NE) { s_vn[t] = evn[t]; s_cn[t] = ecn[t]; s_sh[t] = esh[t]; }
    if (t < MC) ccnt[t] = 0;
    if (t < NV) vcnt[t] = 0;
    __syncthreads();
    if (t < NE) { atomicAdd(&ccnt[s_cn[t]], 1); atomicAdd(&vcnt[s_vn[t]], 1); }
    __syncthreads();
    if (t == 0) {
        int run = 0;
        for (int c = 0; c < MC; ++c) { cbase[c] = run; run += ccnt[c]; }
        run = 0;
        for (int n = 0; n < NV; ++n) { vbase[n] = run; g_vnptr[n] = run; run += vcnt[n]; }
        g_vnptr[NV] = run;
    }
    __syncthreads();
    if (t < NE) {
        int c = s_cn[t], v = s_vn[t];
        int pc = 0, pv = 0;
        for (int e2 = 0; e2 < t; ++e2) {     // stable (e-ascending) position
            pc += (s_cn[e2] == c);
            pv += (s_vn[e2] == v);
        }
        const int pos = cbase[c] + pc;
        g_czo[pos] = v * ZL2 + (ZL - s_sh[t]);
        g_ceo[pos] = t * ZL2;
        g_vpack[vbase[v] + pv] = (t * ZL2) | (s_sh[t] << 20);
    }
}

// ---------------------------------------------------------------------------
// Prime: tot = xa, written doubled (both row halves). One-shot before iter 0.
// ---------------------------------------------------------------------------
__global__ __launch_bounds__(512) void k_prime(const float* __restrict__ xa) {
    const int idx = blockIdx.x * 512 + threadIdx.x;   // over BB*NV*ZW quads
    if (idx >= BB * NV * ZW) return;
    const int row = idx / ZW;       // b*NV + n
    const int q = idx - row * ZW;
    const float4 v = ((const float4*)xa)[idx];
    float4* __restrict__ d = (float4*)g_tot + (size_t)row * ZW2;
    d[q] = v;
    d[q + ZW] = v;
}

// ---------------------------------------------------------------------------
// VN update with PRE-ALIGNED shared staging. During staging each edge's 16
// needed words are funnelshifted to quad alignment, so the inner loop is
// 1 LDS + 4 sign-extract adds per edge. Integer accumulation is exact.
// Writes tot DOUBLED and out[it-1][b][z][n] via shared transpose.
// ---------------------------------------------------------------------------
__global__ __launch_bounds__(512, 3) void k_vn(const float* __restrict__ xa,
                                               float* __restrict__ out_prev,
                                               int write_out, int write_tot) {
    __shared__ __align__(16) float s[NV][68];    // padded transpose rows
    __shared__ unsigned seg[NE * SEGP];          // pre-aligned edge segments (25 KB)
    __shared__ int svptr[NV + 1];
    __shared__ int svpack[NE];
    const int tx = threadIdx.x;           // quad within tile (16)
    const int ty = threadIdx.y;           // n-group (32)
    const int tid = ty * 16 + tx;
    const int b = blockIdx.y;
    const int q0 = blockIdx.x * 16;       // quad tile base
    const int q = q0 + tx;
    const int z0 = q0 * 4;                // z tile base

    for (int i = tid; i <= NV; i += 512) svptr[i] = g_vnptr[i];
    for (int i = tid; i < NE; i += 512) svpack[i] = g_vpack[i];
    __syncthreads();

    // Stage pre-aligned: seg[j*17 + w] = bytes (z0 + 4w + sh_j ..+3) of edge
    // j's doubled row, for w = 0..15. Second operand index <= 191, in-bounds.
    const unsigned* __restrict__ eqw =
        (const unsigned*)(g_extq + (size_t)b * (NE * ZL2));
#pragma unroll
    for (int p = 0; p < 12; ++p) {
        const int idx = tid + p * 512;
        if (idx < NE * 16) {
            const int j = idx >> 4;
            const int w = idx & 15;
            const int pk = svpack[j];
            const int sh = pk >> 20;
            const int wb = ((pk & 0xFFFFF) >> 2) + ((z0 + sh) >> 2);
            seg[j * SEGP + w] =
                __funnelshift_r(eqw[wb + w], eqw[wb + w + 1], (sh & 3) * 8);
        }
    }
    __syncthreads();

    float* __restrict__ tb = g_tot + (size_t)b * (NV * ZL2);

    for (int n = ty; n < NV; n += 32) {
        float4 ch = ((const float4*)xa)[((size_t)b * NV + n) * ZW + q];
        int a0 = 0, a1 = 0, a2 = 0, a3 = 0;   // exact integer sums
        const int j1 = svptr[n + 1];
        for (int j = svptr[n]; j < j1; ++j) {
            const unsigned u = seg[j * SEGP + tx];   // pre-aligned quad
            a0 += (int)(signed char)(u);
            a1 += (int)(signed char)(u >> 8);
            a2 += (int)(signed char)(u >> 16);
            a3 += (int)(signed char)(u >> 24);
        }
        ch.x += 0.5f * (float)a0;
        ch.y += 0.5f * (float)a1;
        ch.z += 0.5f * (float)a2;
        ch.w += 0.5f * (float)a3;
        if (write_tot) {
            float4* __restrict__ tr = (float4*)tb + n * ZW2;
            tr[q] = ch;
            tr[q + ZW] = ch;
        }
        *(float4*)&s[n][tx * 4] = ch;
    }
    if (write_out) {
        __syncthreads();
        float4* __restrict__ dst = (float4*)(out_prev + ((size_t)b * ZL + z0) * NV);
        // 64 z-rows x 17 float4 per row (NV=68)
        for (int f = tid; f < 64 * 17; f += 512) {
            const int zl = f / 17;
            const int n0 = (f - zl * 17) * 4;
            float4 o;
            o.x = s[n0 + 0][zl]; o.y = s[n0 + 1][zl];
            o.z = s[n0 + 2][zl]; o.w = s[n0 + 3][zl];
            dst[f] = o;
        }
    }
}

// ---------------------------------------------------------------------------
// CN update (min-sum, reference-exact tie semantics) + LUT quantizer.
// One block per (CN, batch): 192 threads = 192 z-pairs. Doubled tot rows ->
// wrap-free gather; writes state DUPLICATED (z2 and z2+ZL) so k_vn's gather
// is wrap-free too. Output pair = one byte_perm over {+m1,-m1,+m2,-m2} LUTs.
// ---------------------------------------------------------------------------
__global__ __launch_bounds__(192, 6) void k_cn(const float* __restrict__ cnw,
                                               int it, int first) {
    __shared__ int szo[8], seo[8];
    const int tid = threadIdx.x;
    const int c = blockIdx.x;
    const int b = blockIdx.y;
    if (tid < 8) {
        szo[tid] = g_czo[c * 8 + tid];
        seo[tid] = g_ceo[c * 8 + tid];
    }
    __syncthreads();

    const int z2 = tid * 2;
    const float w = __ldg(&cnw[it]);
    const float w2m = fabsf(w + w);
    const unsigned wsb = __float_as_uint(w) & 0x80000000u;
    const float* __restrict__ tbr = g_tot + (size_t)b * (NV * ZL2);
    signed char* __restrict__ eqz = g_extq + (size_t)b * (NE * ZL2) + z2;

    // Pass A: batch all loads (16 tot floats + 8 state shorts in flight)
    float t0[8], t1[8];
    int es[8];
#pragma unroll
    for (int j = 0; j < 8; ++j) {
        const int za = szo[j] + z2;        // wrap-free (doubled rows)
        t0[j] = tbr[za];
        t1[j] = tbr[za + 1];
        es[j] = first ? 0 : (int)*(const short*)(eqz + seo[j]);
    }
    // Pass B: extrinsic beliefs, sign XOR, min1
    float v0[8], v1[8];
    unsigned s0 = wsb, s1 = wsb;          // running sign XOR (w sign folded)
    float m10 = 1e30f, m11 = 1e30f;
#pragma unroll
    for (int j = 0; j < 8; ++j) {
        const float c0 = 0.5f * (float)((signed char)(es[j]));
        const float c1 = 0.5f * (float)((signed char)(es[j] >> 8));
        const float a0 = fminf(fmaxf(t0[j] - c0, -20.f), 20.f);
        const float a1 = fminf(fmaxf(t1[j] - c1, -20.f), 20.f);
        v0[j] = a0; v1[j] = a1;
        s0 ^= __float_as_uint(a0);
        s1 ^= __float_as_uint(a1);
        m10 = fminf(m10, fabsf(a0));
        m11 = fminf(m11, fabsf(a1));
    }
    float m20 = 1e9f, m21 = 1e9f;         // BIG, matches reference when all tie
#pragma unroll
    for (int j = 0; j < 8; ++j) {
        float a;
        a = fabsf(v0[j]); if (a != m10) m20 = fminf(m20, a);
        a = fabsf(v1[j]); if (a != m11) m21 = fminf(m21, a);
    }
    // Quantized magnitudes (stored value = 2*q in [-15,15]):
    // __float2int_rn = round-half-even; clip-then-round == round-then-clip @15.
    const int i10 = __float2int_rn(fminf(w2m * m10, 15.f));
    const int i20 = __float2int_rn(fminf(w2m * m20, 15.f));
    const int i11 = __float2int_rn(fminf(w2m * m11, 15.f));
    const int i21 = __float2int_rn(fminf(w2m * m21, 15.f));
    // Per-lane byte LUT: [ +m1, -m1, +m2, -m2 ]
    const unsigned lut0 = (unsigned)i10 | (((unsigned)(-i10) & 0xff) << 8)
                        | ((unsigned)i20 << 16) | (((unsigned)(-i20) & 0xff) << 24);
    const unsigned lut1 = (unsigned)i11 | (((unsigned)(-i11) & 0xff) << 8)
                        | ((unsigned)i21 << 16) | (((unsigned)(-i21) & 0xff) << 24);
#pragma unroll
    for (int j = 0; j < 8; ++j) {
        const unsigned u0 = s0 ^ __float_as_uint(v0[j]);
        const unsigned u1 = s1 ^ __float_as_uint(v1[j]);
        int idx0 = (int)(u0 >> 31);       // sign bit
        if (fabsf(v0[j]) == m10) idx0 |= 2;   // is-min -> use m2
        int idx1 = (int)(u1 >> 31) | 4;   // select from lut1
        if (fabsf(v1[j]) == m11) idx1 |= 2;
        const unsigned r = __byte_perm(lut0, lut1, (unsigned)(idx0 | (idx1 << 4)));
        *(short*)(eqz + seo[j]) = (short)r;          // copy 1
        *(short*)(eqz + seo[j] + ZL) = (short)r;     // copy 2 (wrap-free reads)
    }
}

// ---------------------------------------------------------------------------
extern "C" void kernel_launch(void* const* d_in, const int* in_sizes, int n_in,
                              void* d_out, int out_size) {
    const float* xa  = (const float*)d_in[0];   // [B, N, Z] f32
    const float* cnw = (const float*)d_in[1];   // [ITERS] f32
    const int* evn   = (const int*)d_in[2];     // [E] i32
    const int* ecn   = (const int*)d_in[3];     // [E] i32
    const int* esh   = (const int*)d_in[4];     // [E] i32
    float* out = (float*)d_out;                 // [ITERS, B, Z, N] f32

    k_setup<<<1, 384>>>(evn, ecn, esh);
    k_prime<<<(BB * NV * ZW + 511) / 512, 512>>>(xa);   // tot = xa (doubled rows)

    dim3 blkV(16, 32);
    dim3 gV(6, BB);                 // 6 quad-tiles of 16 quads (64 z) x batch
    dim3 gC(MC, BB);                // one block per (CN, batch), 192 z-pairs

    for (int it = 0; it < ITERS; ++it) {
        k_cn<<<gC, 192>>>(cnw, it, it == 0);
        // VN pass of iteration it+1 writes out[it] (== marginalized output of
        // it); the last one needs no tot for a subsequent CN pass.
        k_vn<<<gV, blkV>>>(xa, out + (size_t)it * BB * ZL * NV, 1,
                           it != ITERS - 1);
    }
}

// round 16
// speedup vs baseline: 1.1691x; 1.0627x over previous
#include <cuda_runtime.h>

// Problem constants (fixed by this dataset instance)
#define ITERS 5
#define NV 68      // base VNs
#define MC 46      // base CNs
#define ZL 384     // lifting size
#define NE 368     // edges (= MC*8, regular degree-8 checks by construction)
#define BB 64      // batch
#define ZW (ZL/4)  // 96 words per edge row
#define ZL2 (2*ZL) // doubled tot-row length (wrap-free k_cn gather)
#define ZW2 (2*ZW)

// Persistent scratch (no allocations allowed)
// g_extq rows are stored PRE-ROTATED into the VN z-domain:
//   C[e][u] = message m_e((u + sh_e) mod ZL), u in [0, ZL)
// so k_vn reads word q of row e directly (aligned, shift-free).
__device__ __align__(16) signed char g_extq[BB * NE * ZL];
__device__ __align__(16) float       g_tot [BB * NV * ZL2];  // beliefs, DOUBLED rows
// CN-ordered per-edge metadata (uniform per CN-block in k_cn)
__device__ int g_czo[NE];   // vn*2*ZL + (ZL - shift)  -> wrap-free tot gather base
__device__ int g_ceb[NE];   // e * ZL       (extq row base)
__device__ int g_cof[NE];   // ZL - shift   (CN->VN domain rotation)
// VN list for k_vn
__device__ int g_vnptr[NV + 1];
__device__ int g_vpack[NE]; // VN-order: e * ZW (word row offset; no shift needed)

// ---------------------------------------------------------------------------
// Setup: build CN-ordered metadata arrays and VN-CSR (deterministic).
// ---------------------------------------------------------------------------
__global__ void k_setup(const int* __restrict__ evn, const int* __restrict__ ecn,
                        const int* __restrict__ esh) {
    __shared__ int s_vn[NE], s_cn[NE], s_sh[NE];
    __shared__ int ccnt[MC], vcnt[NV];
    __shared__ int cbase[MC], vbase[NV];
    int t = threadIdx.x;
    if (t < NE) { s_vn[t] = evn[t]; s_cn[t] = ecn[t]; s_sh[t] = esh[t]; }
    if (t < MC) ccnt[t] = 0;
    if (t < NV) vcnt[t] = 0;
    __syncthreads();
    if (t < NE) { atomicAdd(&ccnt[s_cn[t]], 1); atomicAdd(&vcnt[s_vn[t]], 1); }
    __syncthreads();
    if (t == 0) {
        int run = 0;
        for (int c = 0; c < MC; ++c) { cbase[c] = run; run += ccnt[c]; }
        run = 0;
        for (int n = 0; n < NV; ++n) { vbase[n] = run; g_vnptr[n] = run; run += vcnt[n]; }
        g_vnptr[NV] = run;
    }
    __syncthreads();
    if (t < NE) {
        int c = s_cn[t], v = s_vn[t];
        int pc = 0, pv = 0;
        for (int e2 = 0; e2 < t; ++e2) {     // stable (e-ascending) position
            pc += (s_cn[e2] == c);
            pv += (s_vn[e2] == v);
        }
        const int pos = cbase[c] + pc;
        g_czo[pos] = v * ZL2 + (ZL - s_sh[t]);
        g_ceb[pos] = t * ZL;
        g_cof[pos] = ZL - s_sh[t];
        g_vpack[vbase[v] + pv] = t * ZW;
    }
}

// ---------------------------------------------------------------------------
// Prime: tot = xa, written doubled (both row halves). One-shot before iter 0.
// ---------------------------------------------------------------------------
__global__ __launch_bounds__(512) void k_prime(const float* __restrict__ xa) {
    const int idx = blockIdx.x * 512 + threadIdx.x;   // over BB*NV*ZW quads
    if (idx >= BB * NV * ZW) return;
    const int row = idx / ZW;       // b*NV + n
    const int q = idx - row * ZW;
    const float4 v = ((const float4*)xa)[idx];
    float4* __restrict__ d = (float4*)g_tot + (size_t)row * ZW2;
    d[q] = v;
    d[q + ZW] = v;
}

// ---------------------------------------------------------------------------
// VN update, z-quad per thread. extq rows are pre-rotated to VN domain, so
// each edge is ONE aligned coalesced word load + 4 sign-extract adds.
// Edge loop chunked by 4 for MLP. Integer accumulation is exact.
// Writes tot DOUBLED and out[it-1][b][z][n] via shared transpose.
// ---------------------------------------------------------------------------
__global__ __launch_bounds__(512, 3) void k_vn(const float* __restrict__ xa,
                                               float* __restrict__ out_prev,
                                               int write_out, int write_tot) {
    __shared__ __align__(16) float s[NV][68];    // padded transpose rows
    __shared__ int svptr[NV + 1];
    __shared__ int svpack[NE];
    const int tx = threadIdx.x;           // quad within tile (16)
    const int ty = threadIdx.y;           // n-group (32)
    const int tid = ty * 16 + tx;
    const int b = blockIdx.y;
    const int q0 = blockIdx.x * 16;       // quad tile base
    const int q = q0 + tx;
    const int z0 = q0 * 4;                // z tile base

    for (int i = tid; i <= NV; i += 512) svptr[i] = g_vnptr[i];
    for (int i = tid; i < NE; i += 512) svpack[i] = g_vpack[i];
    __syncthreads();

    const unsigned* __restrict__ eqw =
        (const unsigned*)(g_extq + (size_t)b * (NE * ZL));
    float* __restrict__ tb = g_tot + (size_t)b * (NV * ZL2);

    for (int n = ty; n < NV; n += 32) {
        float4 ch = ((const float4*)xa)[((size_t)b * NV + n) * ZW + q];
        int a0 = 0, a1 = 0, a2 = 0, a3 = 0;   // exact integer sums
        int j = svptr[n];
        const int j1 = svptr[n + 1];
        while (j < j1) {
            const int cnt = j1 - j;            // >=1
            unsigned u[4];
#pragma unroll
            for (int k = 0; k < 4; ++k)        // pass A: batched loads (MLP 4)
                if (k < cnt) u[k] = eqw[svpack[j + k] + q];
#pragma unroll
            for (int k = 0; k < 4; ++k) {      // pass B: consume
                if (k < cnt) {
                    a0 += (int)(signed char)(u[k]);
                    a1 += (int)(signed char)(u[k] >> 8);
                    a2 += (int)(signed char)(u[k] >> 16);
                    a3 += (int)(signed char)(u[k] >> 24);
                }
            }
            j += 4;
        }
        ch.x += 0.5f * (float)a0;
        ch.y += 0.5f * (float)a1;
        ch.z += 0.5f * (float)a2;
        ch.w += 0.5f * (float)a3;
        if (write_tot) {
            float4* __restrict__ tr = (float4*)tb + n * ZW2;
            tr[q] = ch;
            tr[q + ZW] = ch;
        }
        *(float4*)&s[n][tx * 4] = ch;
    }
    if (write_out) {
        __syncthreads();
        float4* __restrict__ dst = (float4*)(out_prev + ((size_t)b * ZL + z0) * NV);
        // 64 z-rows x 17 float4 per row (NV=68)
        for (int f = tid; f < 64 * 17; f += 512) {
            const int zl = f / 17;
            const int n0 = (f - zl * 17) * 4;
            float4 o;
            o.x = s[n0 + 0][zl]; o.y = s[n0 + 1][zl];
            o.z = s[n0 + 2][zl]; o.w = s[n0 + 3][zl];
            dst[f] = o;
        }
    }
}

// ---------------------------------------------------------------------------
// CN update (min-sum, reference-exact tie semantics) + LUT quantizer.
// One block per (CN, batch): 192 threads = 192 z-pairs. Doubled tot rows ->
// wrap-free belief gather. State is stored ROTATED to VN domain: this kernel
// reads/writes its own messages at u = (zc - sh) mod ZL via per-edge uniform
// rotation offsets (byte loads/stores; addresses computed once, reused).
// ---------------------------------------------------------------------------
__global__ __launch_bounds__(192, 6) void k_cn(const float* __restrict__ cnw,
                                               int it, int first) {
    __shared__ int szo[8], seb[8], sof[8];
    const int tid = threadIdx.x;
    const int c = blockIdx.x;
    const int b = blockIdx.y;
    if (tid < 8) {
        szo[tid] = g_czo[c * 8 + tid];
        seb[tid] = g_ceb[c * 8 + tid];
        sof[tid] = g_cof[c * 8 + tid];
    }
    __syncthreads();

    const int z2 = tid * 2;
    const float w = __ldg(&cnw[it]);
    const float w2m = fabsf(w + w);
    const unsigned wsb = __float_as_uint(w) & 0x80000000u;
    const float* __restrict__ tbr = g_tot + (size_t)b * (NV * ZL2);
    signed char* __restrict__ eqb = g_extq + (size_t)b * (NE * ZL);

    // Rotated state addresses (computed once; used for load and store)
    int ea0[8], ea1[8];
    // Pass A: batch all loads (16 tot floats + 16 state bytes in flight)
    float t0[8], t1[8];
    int es0[8], es1[8];
#pragma unroll
    for (int j = 0; j < 8; ++j) {
        const int za = szo[j] + z2;        // wrap-free (doubled tot rows)
        t0[j] = tbr[za];
        t1[j] = tbr[za + 1];
        int u0 = sof[j] + z2;  if (u0 >= ZL) u0 -= ZL;
        int u1 = sof[j] + z2 + 1; if (u1 >= ZL) u1 -= ZL;
        ea0[j] = seb[j] + u0;
        ea1[j] = seb[j] + u1;
        es0[j] = first ? 0 : (int)eqb[ea0[j]];
        es1[j] = first ? 0 : (int)eqb[ea1[j]];
    }
    // Pass B: extrinsic beliefs, sign XOR, min1
    float v0[8], v1[8];
    unsigned s0 = wsb, s1 = wsb;          // running sign XOR (w sign folded)
    float m10 = 1e30f, m11 = 1e30f;
#pragma unroll
    for (int j = 0; j < 8; ++j) {
        const float c0 = 0.5f * (float)es0[j];
        const float c1 = 0.5f * (float)es1[j];
        const float a0 = fminf(fmaxf(t0[j] - c0, -20.f), 20.f);
        const float a1 = fminf(fmaxf(t1[j] - c1, -20.f), 20.f);
        v0[j] = a0; v1[j] = a1;
        s0 ^= __float_as_uint(a0);
        s1 ^= __float_as_uint(a1);
        m10 = fminf(m10, fabsf(a0));
        m11 = fminf(m11, fabsf(a1));
    }
    float m20 = 1e9f, m21 = 1e9f;         // BIG, matches reference when all tie
#pragma unroll
    for (int j = 0; j < 8; ++j) {
        float a;
        a = fabsf(v0[j]); if (a != m10) m20 = fminf(m20, a);
        a = fabsf(v1[j]); if (a != m11) m21 = fminf(m21, a);
    }
    // Quantized magnitudes (stored value = 2*q in [-15,15]):
    // __float2int_rn = round-half-even; clip-then-round == round-then-clip @15.
    const int i10 = __float2int_rn(fminf(w2m * m10, 15.f));
    const int i20 = __float2int_rn(fminf(w2m * m20, 15.f));
    const int i11 = __float2int_rn(fminf(w2m * m11, 15.f));
    const int i21 = __float2int_rn(fminf(w2m * m21, 15.f));
    // Per-lane byte LUT: [ +m1, -m1, +m2, -m2 ]
    const unsigned lut0 = (unsigned)i10 | (((unsigned)(-i10) & 0xff) << 8)
                        | ((unsigned)i20 << 16) | (((unsigned)(-i20) & 0xff) << 24);
    const unsigned lut1 = (unsigned)i11 | (((unsigned)(-i11) & 0xff) << 8)
                        | ((unsigned)i21 << 16) | (((unsigned)(-i21) & 0xff) << 24);
#pragma unroll
    for (int j = 0; j < 8; ++j) {
        const unsigned u0 = s0 ^ __float_as_uint(v0[j]);
        const unsigned u1 = s1 ^ __float_as_uint(v1[j]);
        int idx0 = (int)(u0 >> 31);       // sign bit
        if (fabsf(v0[j]) == m10) idx0 |= 2;   // is-min -> use m2
        int idx1 = (int)(u1 >> 31) | 4;   // select from lut1
        if (fabsf(v1[j]) == m11) idx1 |= 2;
        const unsigned r = __byte_perm(lut0, lut1, (unsigned)(idx0 | (idx1 << 4)));
        eqb[ea0[j]] = (signed char)(r);          // z2's message (rotated pos)
        eqb[ea1[j]] = (signed char)(r >> 8);     // z2+1's message
    }
}

// ---------------------------------------------------------------------------
extern "C" void kernel_launch(void* const* d_in, const int* in_sizes, int n_in,
                              void* d_out, int out_size) {
    const float* xa  = (const float*)d_in[0];   // [B, N, Z] f32
    const float* cnw = (const float*)d_in[1];   // [ITERS] f32
    const int* evn   = (const int*)d_in[2];     // [E] i32
    const int* ecn   = (const int*)d_in[3];     // [E] i32
    const int* esh   = (const int*)d_in[4];     // [E] i32
    float* out = (float*)d_out;                 // [ITERS, B, Z, N] f32

    k_setup<<<1, 384>>>(evn, ecn, esh);
    k_prime<<<(BB * NV * ZW + 511) / 512, 512>>>(xa);   // tot = xa (doubled rows)

    dim3 blkV(16, 32);
    dim3 gV(6, BB);                 // 6 quad-tiles of 16 quads (64 z) x batch
    dim3 gC(MC, BB);                // one block per (CN, batch), 192 z-pairs

    for (int it = 0; it < ITERS; ++it) {
        k_cn<<<gC, 192>>>(cnw, it, it == 0);
        // VN pass of iteration it+1 writes out[it] (== marginalized output of
        // it); the last one needs no tot for a subsequent CN pass.
        k_vn<<<gV, blkV>>>(xa, out + (size_t)it * BB * ZL * NV, 1,
                           it != ITERS - 1);
    }
}